// round 12
// baseline (speedup 1.0000x reference)
#include <cuda_runtime.h>
#include <cstdint>

// ---------------------------------------------------------------------------
// FeatureFusionModule: B=8, C=512, H=W=64, N=4096, heads=8, d=64
// GEMMs: mma.sync tf32, 4-warp CTA (64x64 warp tiles), cp.async 2-stage,
// ldmatrix from quad-swizzled raw-fp32 SMEM, weights pre-rounded to tf32.
// ---------------------------------------------------------------------------

#define Bb 8
#define Cc 512
#define Nn 4096

// ------------------------------- scratch -----------------------------------
__device__ float g_r   [(size_t)Bb * Nn * Cc];
__device__ float g_x   [(size_t)Bb * Nn * Cc];
__device__ float g_yr  [(size_t)Bb * Nn * 2 * Cc];
__device__ float g_yx  [(size_t)Bb * Nn * 2 * Cc];
__device__ float g_ur  [(size_t)Bb * Nn * Cc];
__device__ float g_ux  [(size_t)Bb * Nn * Cc];
__device__ float g_kvr [(size_t)Bb * Nn * 2 * Cc];
__device__ float g_kvx [(size_t)Bb * Nn * 2 * Cc];
__device__ float g_ctx [2 * 64 * 64 * 64];
__device__ float g_attp[2 * 64 * 16 * 64 * 64];
__device__ float g_fuse[(size_t)Bb * Nn * 2 * Cc];
__device__ float g_res [(size_t)Bb * Nn * Cc];
__device__ float g_t1  [(size_t)Bb * Nn * Cc];
__device__ float g_t2  [(size_t)Bb * Nn * Cc];
__device__ float g_bnp [2 * 256 * Cc];
__device__ float g_mu  [Cc];
__device__ float g_rs  [Cc];
__device__ float g_w   [4456448];          // tf32-rounded weights

// ----------------------------- helpers --------------------------------------
__device__ __forceinline__ uint32_t f2tf32(float f) {
    uint32_t r;
    asm("cvt.rna.tf32.f32 %0, %1;" : "=r"(r) : "f"(f));
    return r;
}
__device__ __forceinline__ uint32_t cvt_u(uint32_t x) {
    uint32_t r;
    asm("cvt.rna.tf32.f32 %0, %1;" : "=r"(r) : "f"(__uint_as_float(x)));
    return r;
}

__device__ __forceinline__ void mma_tf32(float* d, const uint32_t* a, const uint32_t* b) {
    asm volatile(
        "mma.sync.aligned.m16n8k8.row.col.f32.tf32.tf32.f32 "
        "{%0,%1,%2,%3}, {%4,%5,%6,%7}, {%8,%9}, {%0,%1,%2,%3};"
        : "+f"(d[0]), "+f"(d[1]), "+f"(d[2]), "+f"(d[3])
        : "r"(a[0]), "r"(a[1]), "r"(a[2]), "r"(a[3]), "r"(b[0]), "r"(b[1]));
}

#define LDSM4(r0, r1, r2, r3, addr) \
    asm volatile("ldmatrix.sync.aligned.m8n8.x4.shared.b16 {%0,%1,%2,%3}, [%4];" \
        : "=r"(r0), "=r"(r1), "=r"(r2), "=r"(r3) : "r"(addr))

#define CPA16(dst, src) \
    asm volatile("cp.async.cg.shared.global [%0], [%1], 16;" :: "r"(dst), "l"(src))
#define CPCOMMIT() asm volatile("cp.async.commit_group;" ::: "memory")
#define CPWAIT0()  asm volatile("cp.async.wait_group 0;" ::: "memory")

// ------------------------------ tensor-core GEMM ----------------------------
// C[m,n] = act( sum_k A[m,k]*Bw[n,k] + bias[n] + resid[m,n] )
// CTA tile 128x128, 4 warps (2x2), warp tile 64x64, k-chunk 16, 2 cp.async
// stages. SMEM stage (16 KB): A rows 0..127 at r*64B (first 8 KB), B rows at
// 8192 + r*64B. Quad q of row r stored at quad q ^ ((r>>1)&3).
// Weights (B side) pre-rounded to tf32 in gmem; A fragments cvt.rna'd after
// ldmatrix -> math bitwise-identical to staging-cvt versions (R5/R9).
// Column-split at n=512 (C2 != null) for fused [y|u] proj and res||ce1.
__global__ __launch_bounds__(128, 2) void tc_gemm(
    const float* __restrict__ A, int lda,
    const float* __restrict__ Bw, const float* __restrict__ Bw2, int ldb,
    const float* __restrict__ bias, const float* __restrict__ bias2,
    const float* __restrict__ resid, int ldr,
    float* __restrict__ C, int ldc, float* __restrict__ C2, int ldc2,
    int K, int relu)
{
    __shared__ uint32_t smemu[2 * 4096];   // 32 KB, 2 stages x 16 KB

    const int tid = threadIdx.x;
    const int wid = tid >> 5, lane = tid & 31;
    const int g = lane >> 2, t4 = lane & 3;
    const int wm = wid >> 1, wn = wid & 1;       // 2 x 2 warp grid
    const int bm = blockIdx.y * 128, bn = blockIdx.x * 128;

    const bool hi = (C2 != nullptr) && (bn >= 512);
    const float* Bwe = hi ? Bw2 : Bw;
    const int bnl = hi ? bn - 512 : bn;
    const float* be = hi ? bias2 : bias;
    float* Ce = hi ? C2 : C;
    const int ldce = hi ? ldc2 : ldc;

    float d[4][8][4];
    #pragma unroll
    for (int i = 0; i < 4; i++)
        #pragma unroll
        for (int j = 0; j < 8; j++)
            #pragma unroll
            for (int r = 0; r < 4; r++) d[i][j][r] = 0.f;

    const uint32_t sbase = (uint32_t)__cvta_generic_to_shared(smemu);

    // ---- staging: thread t owns row t (A) and row t (B), 4 quads each ----
    const int s_sw = (tid >> 1) & 3;
    const float* ag = A   + (size_t)(bm  + tid) * lda;
    const float* bg = Bwe + (size_t)(bnl + tid) * ldb;
    const uint32_t aDst = sbase + tid * 64;
    const uint32_t bDst = sbase + 8192 + tid * 64;

    auto issue = [&](int c, int s) {
        const uint32_t st = (uint32_t)(s * 16384);
        const float* ap = ag + c * 16;
        const float* bp = bg + c * 16;
        #pragma unroll
        for (int q = 0; q < 4; q++) {
            const uint32_t doff = (uint32_t)((q ^ s_sw) << 4);
            CPA16(aDst + st + doff, ap + q * 4);
            CPA16(bDst + st + doff, bp + q * 4);
        }
    };

    // ---- ldmatrix per-lane address components (R9-verified mapping) ----
    const int rowAin = ((lane >> 3) & 1) * 8 + (lane & 7);
    const int qhA = lane >> 4;
    const int rowBin = (lane >> 4) * 8 + (lane & 7);
    const int qhB = (lane >> 3) & 1;
    const int swL = ((lane & 7) >> 1) & 3;
    const uint32_t aAddr0 = sbase + (wm * 64 + rowAin) * 64;
    const uint32_t bAddr0 = sbase + 8192 + (wn * 64 + rowBin) * 64;
    uint32_t qA[2], qB[2];
    #pragma unroll
    for (int ks = 0; ks < 2; ks++) {
        qA[ks] = (uint32_t)(((2 * ks + qhA) ^ swL) << 4);
        qB[ks] = (uint32_t)(((2 * ks + qhB) ^ swL) << 4);
    }

    const int nc = K >> 4;
    issue(0, 0); CPCOMMIT();

    for (int c = 0; c < nc; c++) {
        CPWAIT0();
        __syncthreads();   // stage c&1 ready for all; prior reads of (c+1)&1 done
        if (c + 1 < nc) { issue(c + 1, (c + 1) & 1); CPCOMMIT(); }

        const uint32_t st = (uint32_t)((c & 1) * 16384);
        #pragma unroll
        for (int ks = 0; ks < 2; ks++) {
            uint32_t a[4][4], b[4][4];
            #pragma unroll
            for (int mt = 0; mt < 4; mt++)
                LDSM4(a[mt][0], a[mt][1], a[mt][2], a[mt][3],
                      aAddr0 + st + mt * 1024 + qA[ks]);
            #pragma unroll
            for (int pr = 0; pr < 4; pr++)
                LDSM4(b[pr][0], b[pr][1], b[pr][2], b[pr][3],
                      bAddr0 + st + pr * 1024 + qB[ks]);
            #pragma unroll
            for (int mt = 0; mt < 4; mt++)
                #pragma unroll
                for (int j = 0; j < 4; j++)
                    a[mt][j] = cvt_u(a[mt][j]);
            // B is pre-rounded tf32 in gmem: no cvt needed.
            #pragma unroll
            for (int mt = 0; mt < 4; mt++)
                #pragma unroll
                for (int nt = 0; nt < 8; nt++)
                    mma_tf32(d[mt][nt], a[mt], &b[nt >> 1][(nt & 1) * 2]);
        }
    }

    // epilogue
    const int mbase = wm * 64, nbase = wn * 64;
    #pragma unroll
    for (int mt = 0; mt < 4; mt++) {
        #pragma unroll
        for (int half = 0; half < 2; half++) {
            const int m = bm + mbase + mt * 16 + g + half * 8;
            float* crow = Ce + (size_t)m * ldce;
            const float* rrow = resid ? resid + (size_t)m * ldr : nullptr;
            #pragma unroll
            for (int nt = 0; nt < 8; nt++) {
                const int n = bnl + nbase + nt * 8 + t4 * 2;
                float vx = d[mt][nt][half * 2 + 0];
                float vy = d[mt][nt][half * 2 + 1];
                if (be)   { vx += be[n]; vy += be[n + 1]; }
                if (rrow) { vx += rrow[n]; vy += rrow[n + 1]; }
                if (relu) { vx = fmaxf(vx, 0.f); vy = fmaxf(vy, 0.f); }
                *(float2*)(crow + n) = make_float2(vx, vy);
            }
        }
    }
}

// --------------------- round weights to tf32 (once per launch) --------------
__global__ void round_tf32(const float* __restrict__ in, float* __restrict__ out, int n) {
    int i = blockIdx.x * 256 + threadIdx.x;
    if (i < n) out[i] = __uint_as_float(f2tf32(in[i]));
}

// ------------------------- transpose NCHW -> (B,N,C) ------------------------
__global__ void transpose_cn_to_nc(const float* __restrict__ in, float* __restrict__ out) {
    __shared__ float tile[32][33];
    int b = blockIdx.z;
    int n0 = blockIdx.x * 32, c0 = blockIdx.y * 32;
    const float* ip = in + (size_t)b * Cc * Nn;
    float* op = out + (size_t)b * Nn * Cc;
    int tx = threadIdx.x, ty = threadIdx.y;
    #pragma unroll
    for (int i = ty; i < 32; i += 8)
        tile[i][tx] = ip[(size_t)(c0 + i) * Nn + n0 + tx];
    __syncthreads();
    #pragma unroll
    for (int i = ty; i < 32; i += 8)
        op[(size_t)(n0 + i) * Cc + c0 + tx] = tile[tx][i];
}

// --------------------------- attention: kT v partials -----------------------
__global__ __launch_bounds__(256) void attn_ktv(const float* __restrict__ kv,
                                                float* __restrict__ part) {
    __shared__ float ks[32][68];
    __shared__ float vs[32][68];
    int bh = blockIdx.x;
    int b = bh >> 3, h = bh & 7;
    int s = blockIdx.y;
    const float* kp = kv + (size_t)b * Nn * 1024 + h * 64;
    const float* vp = kp + 512;
    int tid = threadIdx.x;
    int td = tid >> 4, te = tid & 15;
    float acc[4][4];
    #pragma unroll
    for (int i = 0; i < 4; i++)
        #pragma unroll
        for (int j = 0; j < 4; j++) acc[i][j] = 0.f;

    for (int n0 = s * 256; n0 < s * 256 + 256; n0 += 32) {
        #pragma unroll
        for (int hh = 0; hh < 2; hh++) {
            int flat = tid + 256 * hh;
            int row = flat >> 4;
            int cv = (flat & 15) << 2;
            *(float4*)&ks[row][cv] = *(const float4*)(kp + (size_t)(n0 + row) * 1024 + cv);
            *(float4*)&vs[row][cv] = *(const float4*)(vp + (size_t)(n0 + row) * 1024 + cv);
        }
        __syncthreads();
        #pragma unroll
        for (int nn = 0; nn < 32; nn++) {
            float av[4], bv[4];
            float4 a4 = *(float4*)&ks[nn][td * 4];
            av[0]=a4.x; av[1]=a4.y; av[2]=a4.z; av[3]=a4.w;
            float4 b4 = *(float4*)&vs[nn][te * 4];
            bv[0]=b4.x; bv[1]=b4.y; bv[2]=b4.z; bv[3]=b4.w;
            #pragma unroll
            for (int i = 0; i < 4; i++)
                #pragma unroll
                for (int j = 0; j < 4; j++)
                    acc[i][j] += av[i] * bv[j];
        }
        __syncthreads();
    }
    float* pp = part + ((size_t)bh * 16 + s) * 4096;
    #pragma unroll
    for (int i = 0; i < 4; i++)
        #pragma unroll
        for (int j = 0; j < 4; j++)
            pp[(td * 4 + i) * 64 + te * 4 + j] = acc[i][j];
}

__global__ void attn_reduce_softmax(const float* __restrict__ part,
                                    float* __restrict__ ctx) {
    int bh = blockIdx.x;
    int e = threadIdx.x;
    float m[64];
    #pragma unroll
    for (int d = 0; d < 64; d++) {
        float ssum = 0.f;
        #pragma unroll
        for (int p = 0; p < 16; p++)
            ssum += part[((size_t)bh * 16 + p) * 4096 + d * 64 + e];
        m[d] = ssum * 0.125f;
    }
    float mx = -1e30f;
    #pragma unroll
    for (int d = 0; d < 64; d++) mx = fmaxf(mx, m[d]);
    float sum = 0.f;
    #pragma unroll
    for (int d = 0; d < 64; d++) { m[d] = expf(m[d] - mx); sum += m[d]; }
    float inv = 1.f / sum;
    #pragma unroll
    for (int d = 0; d < 64; d++)
        ctx[(size_t)bh * 4096 + d * 64 + e] = m[d] * inv;
}

__global__ __launch_bounds__(256) void attn_qctx(const float* __restrict__ q,
                                                 const float* __restrict__ ctx,
                                                 float* __restrict__ outp) {
    __shared__ float cs[64][68];
    __shared__ float qs[64][68];
    int bh = blockIdx.y;
    int b = bh >> 3, h = bh & 7;
    const float* cp = ctx + (size_t)bh * 4096;
    int tid = threadIdx.x;
    for (int i = tid; i < 4096; i += 256)
        cs[i >> 6][i & 63] = cp[i];
    int n0 = blockIdx.x * 64;
    const float* qp = q + (size_t)b * Nn * Cc + h * 64;
    #pragma unroll
    for (int j = 0; j < 4; j++) {
        int flat = tid + 256 * j;
        int row = flat >> 4;
        int cv = (flat & 15) << 2;
        *(float4*)&qs[row][cv] = *(const float4*)(qp + (size_t)(n0 + row) * Cc + cv);
    }
    __syncthreads();
    int tn = tid >> 3;
    int te = tid & 7;
    float acc0[8], acc1[8];
    #pragma unroll
    for (int j = 0; j < 8; j++) { acc0[j] = 0.f; acc1[j] = 0.f; }
    #pragma unroll 4
    for (int d = 0; d < 64; d++) {
        float qa = qs[tn][d];
        float qb = qs[tn + 32][d];
        float4 c0 = *(float4*)&cs[d][te * 8];
        float4 c1 = *(float4*)&cs[d][te * 8 + 4];
        float cv[8];
        cv[0]=c0.x; cv[1]=c0.y; cv[2]=c0.z; cv[3]=c0.w;
        cv[4]=c1.x; cv[5]=c1.y; cv[6]=c1.z; cv[7]=c1.w;
        #pragma unroll
        for (int j = 0; j < 8; j++) {
            acc0[j] += qa * cv[j];
            acc1[j] += qb * cv[j];
        }
    }
    float* o0 = outp + ((size_t)b * Nn + n0 + tn) * 1024 + h * 64 + te * 8;
    float* o1 = outp + ((size_t)b * Nn + n0 + tn + 32) * 1024 + h * 64 + te * 8;
    #pragma unroll
    for (int j = 0; j < 8; j++) { o0[j] = acc0[j]; o1[j] = acc1[j]; }
}

// ------------------------------ layernorm rows ------------------------------
__global__ __launch_bounds__(128) void layernorm_rows(float* __restrict__ base, int ld,
                                                      const float* __restrict__ gg,
                                                      const float* __restrict__ bb) {
    int row = blockIdx.x;
    float* p = base + (size_t)row * ld;
    int t = threadIdx.x;
    float v[4];
    float s = 0.f;
    #pragma unroll
    for (int i = 0; i < 4; i++) { v[i] = p[t + i * 128]; s += v[i]; }
    __shared__ float red[4];
    #pragma unroll
    for (int o = 16; o > 0; o >>= 1) s += __shfl_xor_sync(0xffffffffu, s, o);
    if ((t & 31) == 0) red[t >> 5] = s;
    __syncthreads();
    float mu = (red[0] + red[1] + red[2] + red[3]) * (1.f / 512.f);
    float q = 0.f;
    #pragma unroll
    for (int i = 0; i < 4; i++) { float d = v[i] - mu; q += d * d; }
    #pragma unroll
    for (int o = 16; o > 0; o >>= 1) q += __shfl_xor_sync(0xffffffffu, q, o);
    __syncthreads();
    if ((t & 31) == 0) red[t >> 5] = q;
    __syncthreads();
    float rs = rsqrtf((red[0] + red[1] + red[2] + red[3]) * (1.f / 512.f) + 1e-5f);
    #pragma unroll
    for (int i = 0; i < 4; i++) {
        int c = t + i * 128;
        p[c] = (v[i] - mu) * rs * gg[c] + bb[c];
    }
}

// --------------------------- depthwise 3x3 + relu ---------------------------
__global__ void dwconv3x3(const float* __restrict__ in, const float* __restrict__ w,
                          const float* __restrict__ bias, float* __restrict__ out) {
    int idx = blockIdx.x * 256 + threadIdx.x;
    int c = idx & 511;
    int n = (idx >> 9) & 4095;
    int b = idx >> 21;
    int h = n >> 6, ww = n & 63;
    float acc = bias[c];
    #pragma unroll
    for (int kh = 0; kh < 3; kh++) {
        int hh = h + kh - 1;
        if ((unsigned)hh >= 64u) continue;
        #pragma unroll
        for (int kw = 0; kw < 3; kw++) {
            int wc = ww + kw - 1;
            if ((unsigned)wc >= 64u) continue;
            acc += in[((size_t)b * Nn + hh * 64 + wc) * Cc + c] * w[c * 9 + kh * 3 + kw];
        }
    }
    out[idx] = fmaxf(acc, 0.f);
}

// ------------------------------- batchnorm ----------------------------------
__global__ __launch_bounds__(256) void bn_stats_partial(const float* __restrict__ X,
                                                        float* __restrict__ part) {
    int blk = blockIdx.x;
    const float* p = X + (size_t)blk * 128 * Cc;
    int c0 = threadIdx.x, c1 = threadIdx.x + 256;
    float s0 = 0.f, q0 = 0.f, s1 = 0.f, q1 = 0.f;
    for (int r = 0; r < 128; r++) {
        float a = p[(size_t)r * Cc + c0];
        s0 += a; q0 += a * a;
        float bv = p[(size_t)r * Cc + c1];
        s1 += bv; q1 += bv * bv;
    }
    part[(size_t)blk * Cc + c0] = s0;
    part[(size_t)blk * Cc + c1] = s1;
    part[(size_t)256 * Cc + blk * Cc + c0] = q0;
    part[(size_t)256 * Cc + blk * Cc + c1] = q1;
}

__global__ void bn_stats_final(const float* __restrict__ part,
                               float* __restrict__ mu, float* __restrict__ rs) {
    int c = threadIdx.x;
    float s = 0.f, q = 0.f;
    for (int p = 0; p < 256; p++) {
        s += part[(size_t)p * Cc + c];
        q += part[(size_t)256 * Cc + p * Cc + c];
    }
    float m = s * (1.f / 32768.f);
    float v = q * (1.f / 32768.f) - m * m;
    mu[c] = m;
    rs[c] = rsqrtf(v + 1e-5f);
}

__global__ void bn_apply_add(const float* __restrict__ t3, const float* __restrict__ res,
                             const float* __restrict__ mu, const float* __restrict__ rs,
                             const float* __restrict__ gg, const float* __restrict__ bb,
                             float* __restrict__ s) {
    int idx = blockIdx.x * 256 + threadIdx.x;
    int c = idx & 511;
    s[idx] = res[idx] + (t3[idx] - mu[c]) * rs[c] * gg[c] + bb[c];
}

__global__ void bn_apply_transpose(const float* __restrict__ s,
                                   const float* __restrict__ mu, const float* __restrict__ rs,
                                   const float* __restrict__ gg, const float* __restrict__ bb,
                                   float* __restrict__ out) {
    __shared__ float tile[32][33];
    int b = blockIdx.z;
    int n0 = blockIdx.x * 32, c0 = blockIdx.y * 32;
    const float* ps = s + (size_t)b * Nn * Cc;
    float* po = out + (size_t)b * Cc * Nn;
    int tx = threadIdx.x, ty = threadIdx.y;
    #pragma unroll
    for (int i = ty; i < 32; i += 8) {
        int c = c0 + tx;
        float v = ps[(size_t)(n0 + i) * Cc + c];
        tile[i][tx] = (v - mu[c]) * rs[c] * gg[c] + bb[c];
    }
    __syncthreads();
    #pragma unroll
    for (int i = ty; i < 32; i += 8)
        po[(size_t)(c0 + i) * Nn + n0 + tx] = tile[tx][i];
}

// --------------------------------- launch -----------------------------------
static void tc_go(const float* A, int lda,
                  const float* Bw, const float* Bw2, int ldb,
                  const float* bias, const float* bias2,
                  const float* resid, int ldr,
                  float* C, int ldc, float* C2, int ldc2,
                  int M, int Ngemm, int K, int relu) {
    tc_gemm<<<dim3(Ngemm / 128, M / 128), 128>>>(
        A, lda, Bw, Bw2, ldb, bias, bias2, resid, ldr, C, ldc, C2, ldc2, K, relu);
}

extern "C" void kernel_launch(void* const* d_in, const int* in_sizes, int n_in,
                              void* d_out, int out_size) {
    (void)in_sizes; (void)n_in; (void)out_size;
    const float* rgb        = (const float*)d_in[0];
    const float* x          = (const float*)d_in[1];
    const float* W_rgb_proj = (const float*)d_in[2];
    const float* b_rgb_proj = (const float*)d_in[3];
    const float* W_x_proj   = (const float*)d_in[4];
    const float* b_x_proj   = (const float*)d_in[5];
    const float* W_kv_rgb   = (const float*)d_in[6];
    const float* W_kv_x     = (const float*)d_in[7];
    const float* W_out_rgb  = (const float*)d_in[8];
    const float* b_out_rgb  = (const float*)d_in[9];
    const float* W_out_x    = (const float*)d_in[10];
    const float* b_out_x    = (const float*)d_in[11];
    const float* ln_rgb_g   = (const float*)d_in[12];
    const float* ln_rgb_b   = (const float*)d_in[13];
    const float* ln_x_g     = (const float*)d_in[14];
    const float* ln_x_b     = (const float*)d_in[15];
    const float* W_res      = (const float*)d_in[16];
    const float* W_ce1      = (const float*)d_in[17];
    const float* b_ce1      = (const float*)d_in[18];
    const float* W_dw       = (const float*)d_in[19];
    const float* b_dw       = (const float*)d_in[20];
    const float* W_ce2      = (const float*)d_in[21];
    const float* b_ce2      = (const float*)d_in[22];
    const float* bn1_g      = (const float*)d_in[23];
    const float* bn1_b      = (const float*)d_in[24];
    const float* bn2_g      = (const float*)d_in[25];
    const float* bn2_b      = (const float*)d_in[26];
    float* out = (float*)d_out;

    float *p_r, *p_x, *p_yr, *p_yx, *p_ur, *p_ux, *p_kvr, *p_kvx;
    float *p_ctx, *p_attp, *p_fuse, *p_res, *p_t1, *p_t2, *p_bnp, *p_mu, *p_rs, *p_w;
    cudaGetSymbolAddress((void**)&p_r,    g_r);
    cudaGetSymbolAddress((void**)&p_x,    g_x);
    cudaGetSymbolAddress((void**)&p_yr,   g_yr);
    cudaGetSymbolAddress((void**)&p_yx,   g_yx);
    cudaGetSymbolAddress((void**)&p_ur,   g_ur);
    cudaGetSymbolAddress((void**)&p_ux,   g_ux);
    cudaGetSymbolAddress((void**)&p_kvr,  g_kvr);
    cudaGetSymbolAddress((void**)&p_kvx,  g_kvx);
    cudaGetSymbolAddress((void**)&p_ctx,  g_ctx);
    cudaGetSymbolAddress((void**)&p_attp, g_attp);
    cudaGetSymbolAddress((void**)&p_fuse, g_fuse);
    cudaGetSymbolAddress((void**)&p_res,  g_res);
    cudaGetSymbolAddress((void**)&p_t1,   g_t1);
    cudaGetSymbolAddress((void**)&p_t2,   g_t2);
    cudaGetSymbolAddress((void**)&p_bnp,  g_bnp);
    cudaGetSymbolAddress((void**)&p_mu,   g_mu);
    cudaGetSymbolAddress((void**)&p_rs,   g_rs);
    cudaGetSymbolAddress((void**)&p_w,    g_w);

    // rounded weight copies
    float* w_rgb  = p_w;
    float* w_x    = p_w + 524288;
    float* w_kvr  = p_w + 1048576;
    float* w_kvx  = p_w + 1572864;
    float* w_outr = p_w + 2097152;
    float* w_outx = p_w + 2621440;
    float* w_res  = p_w + 3145728;
    float* w_ce1  = p_w + 3670016;
    float* w_ce2  = p_w + 4194304;
    round_tf32<<<2048, 256>>>(W_rgb_proj, w_rgb,  524288);
    round_tf32<<<2048, 256>>>(W_x_proj,   w_x,    524288);
    round_tf32<<<2048, 256>>>(W_kv_rgb,   w_kvr,  524288);
    round_tf32<<<2048, 256>>>(W_kv_x,     w_kvx,  524288);
    round_tf32<<<2048, 256>>>(W_out_rgb,  w_outr, 524288);
    round_tf32<<<2048, 256>>>(W_out_x,    w_outx, 524288);
    round_tf32<<<2048, 256>>>(W_res,      w_res,  524288);
    round_tf32<<<2048, 256>>>(W_ce1,      w_ce1,  524288);
    round_tf32<<<1024, 256>>>(W_ce2,      w_ce2,  262144);

    dim3 tp_grid(128, 16, 8), tp_blk(32, 8);

    // 1. transposes
    transpose_cn_to_nc<<<tp_grid, tp_blk>>>(rgb, p_r);
    transpose_cn_to_nc<<<tp_grid, tp_blk>>>(x,   p_x);

    // 2. fused projections: cols 0..511 -> y (ld 1024), 512..1023 -> u (ld 512)
    tc_go(p_r, 512, w_rgb, w_rgb + 262144, 512,
          b_rgb_proj, b_rgb_proj + 512, nullptr, 0,
          p_yr, 1024, p_ur, 512, 32768, 1024, 512, 1);
    tc_go(p_x, 512, w_x, w_x + 262144, 512,
          b_x_proj, b_x_proj + 512, nullptr, 0,
          p_yx, 1024, p_ux, 512, 32768, 1024, 512, 1);

    // 3. kv projections
    tc_go(p_ur, 512, w_kvr, nullptr, 512, nullptr, nullptr, nullptr, 0,
          p_kvr, 1024, nullptr, 0, 32768, 1024, 512, 0);
    tc_go(p_ux, 512, w_kvx, nullptr, 512, nullptr, nullptr, nullptr, 0,
          p_kvx, 1024, nullptr, 0, 32768, 1024, 512, 0);

    // 4. attention (exact fp32)
    attn_ktv<<<dim3(64, 16), 256>>>(p_kvr, p_attp);
    attn_ktv<<<dim3(64, 16), 256>>>(p_kvx, p_attp + (size_t)64 * 16 * 4096);
    attn_reduce_softmax<<<64, 64>>>(p_attp,                          p_ctx);
    attn_reduce_softmax<<<64, 64>>>(p_attp + (size_t)64 * 16 * 4096, p_ctx + 64 * 4096);
    attn_qctx<<<dim3(64, 64), 256>>>(p_ur, p_ctx + 64 * 4096, p_yr + 512);  // o_rgb
    attn_qctx<<<dim3(64, 64), 256>>>(p_ux, p_ctx,             p_yx + 512);  // o_x

    // 5. out projections + residual, then LN
    tc_go(p_yr, 1024, w_outr, nullptr, 1024, b_out_rgb, nullptr, p_r, 512,
          p_fuse, 1024, nullptr, 0, 32768, 512, 1024, 0);
    tc_go(p_yx, 1024, w_outx, nullptr, 1024, b_out_x, nullptr, p_x, 512,
          p_fuse + 512, 1024, nullptr, 0, 32768, 512, 1024, 0);
    layernorm_rows<<<32768, 128>>>(p_fuse,       1024, ln_rgb_g, ln_rgb_b);
    layernorm_rows<<<32768, 128>>>(p_fuse + 512, 1024, ln_x_g,   ln_x_b);

    // 6. fused residual + ce1 (split weights), then CE block
    tc_go(p_fuse, 1024, w_res, w_ce1, 1024, nullptr, b_ce1, nullptr, 0,
          p_res, 512, p_t1, 512, 32768, 1024, 1024, 0);
    dwconv3x3<<<65536, 256>>>(p_t1, W_dw, b_dw, p_t2);
    tc_go(p_t2, 512, w_ce2, nullptr, 512, b_ce2, nullptr, nullptr, 0,
          p_t1, 512, nullptr, 0, 32768, 512, 512, 0);

    // 7. bn1, add residual, bn2, final transposed write
    bn_stats_partial<<<256, 256>>>(p_t1, p_bnp);
    bn_stats_final<<<1, 512>>>(p_bnp, p_mu, p_rs);
    bn_apply_add<<<65536, 256>>>(p_t1, p_res, p_mu, p_rs, bn1_g, bn1_b, p_t2);
    bn_stats_partial<<<256, 256>>>(p_t2, p_bnp);
    bn_stats_final<<<1, 512>>>(p_bnp, p_mu, p_rs);
    bn_apply_transpose<<<tp_grid, tp_blk>>>(p_t2, p_mu, p_rs, bn2_g, bn2_b, out);
}

// round 13
// speedup vs baseline: 1.2389x; 1.2389x over previous
#include <cuda_runtime.h>
#include <cstdint>

// ---------------------------------------------------------------------------
// FeatureFusionModule: B=8, C=512, H=W=64, N=4096, heads=8, d=64
// GEMMs: R9 core (8-warp CTA, 64x32 warp tiles, ldmatrix, quad-swizzle) with
// cp.async staging and weights pre-rounded to tf32 in GMEM.
// ---------------------------------------------------------------------------

#define Bb 8
#define Cc 512
#define Nn 4096

// ------------------------------- scratch -----------------------------------
__device__ float g_r   [(size_t)Bb * Nn * Cc];
__device__ float g_x   [(size_t)Bb * Nn * Cc];
__device__ float g_yr  [(size_t)Bb * Nn * 2 * Cc];
__device__ float g_yx  [(size_t)Bb * Nn * 2 * Cc];
__device__ float g_ur  [(size_t)Bb * Nn * Cc];
__device__ float g_ux  [(size_t)Bb * Nn * Cc];
__device__ float g_kvr [(size_t)Bb * Nn * 2 * Cc];
__device__ float g_kvx [(size_t)Bb * Nn * 2 * Cc];
__device__ float g_ctx [2 * 64 * 64 * 64];
__device__ float g_attp[2 * 64 * 16 * 64 * 64];
__device__ float g_fuse[(size_t)Bb * Nn * 2 * Cc];
__device__ float g_res [(size_t)Bb * Nn * Cc];
__device__ float g_t1  [(size_t)Bb * Nn * Cc];
__device__ float g_t2  [(size_t)Bb * Nn * Cc];
__device__ float g_bnp [2 * 256 * Cc];
__device__ float g_mu  [Cc];
__device__ float g_rs  [Cc];
__device__ float g_w   [4456448];          // tf32-rounded weights

// ----------------------------- helpers --------------------------------------
__device__ __forceinline__ uint32_t f2tf32(float f) {
    uint32_t r;
    asm("cvt.rna.tf32.f32 %0, %1;" : "=r"(r) : "f"(f));
    return r;
}
__device__ __forceinline__ uint32_t cvt_u(uint32_t x) {
    uint32_t r;
    asm("cvt.rna.tf32.f32 %0, %1;" : "=r"(r) : "f"(__uint_as_float(x)));
    return r;
}

__device__ __forceinline__ void mma_tf32(float* d, const uint32_t* a, const uint32_t* b) {
    asm volatile(
        "mma.sync.aligned.m16n8k8.row.col.f32.tf32.tf32.f32 "
        "{%0,%1,%2,%3}, {%4,%5,%6,%7}, {%8,%9}, {%0,%1,%2,%3};"
        : "+f"(d[0]), "+f"(d[1]), "+f"(d[2]), "+f"(d[3])
        : "r"(a[0]), "r"(a[1]), "r"(a[2]), "r"(a[3]), "r"(b[0]), "r"(b[1]));
}

#define LDSM4(r0, r1, r2, r3, addr) \
    asm volatile("ldmatrix.sync.aligned.m8n8.x4.shared.b16 {%0,%1,%2,%3}, [%4];" \
        : "=r"(r0), "=r"(r1), "=r"(r2), "=r"(r3) : "r"(addr))

#define CPA16(dst, src) \
    asm volatile("cp.async.cg.shared.global [%0], [%1], 16;" :: "r"(dst), "l"(src))
#define CPCOMMIT() asm volatile("cp.async.commit_group;" ::: "memory")
#define CPWAIT0()  asm volatile("cp.async.wait_group 0;" ::: "memory")

// ------------------------------ tensor-core GEMM ----------------------------
// C[m,n] = act( sum_k A[m,k]*Bw[n,k] + bias[n] + resid[m,n] )
// Block tile 128x128, 8 warps (2m x 4n), warp tile 64x32, k-chunk 16,
// double-buffered cp.async staging (raw fp32; B pre-rounded tf32 in gmem,
// A cvt.rna'd post-ldmatrix -> math identical to R9).
// SMEM (32 KB): A stages at bytes [0,8K)+[8K,16K), B at [16K,24K)+[24K,32K).
// Row r occupies 64 B; word-quad q of row r stored at quad q ^ ((r>>1)&3).
// Column-split at n=512 (C2 != null) for fused [y|u] proj and res||ce1.
__global__ __launch_bounds__(256, 2) void tc_gemm(
    const float* __restrict__ A, int lda,
    const float* __restrict__ Bw, const float* __restrict__ Bw2, int ldb,
    const float* __restrict__ bias, const float* __restrict__ bias2,
    const float* __restrict__ resid, int ldr,
    float* __restrict__ C, int ldc, float* __restrict__ C2, int ldc2,
    int K, int relu)
{
    __shared__ uint32_t smemu[8192];   // 32 KB

    const int tid = threadIdx.x;
    const int wid = tid >> 5, lane = tid & 31;
    const int g = lane >> 2, t4 = lane & 3;
    const int wm = wid >> 2, wn = wid & 3;       // 2 x 4 warp grid
    const int bm = blockIdx.y * 128, bn = blockIdx.x * 128;

    const bool hi = (C2 != nullptr) && (bn >= 512);
    const float* Bwe = hi ? Bw2 : Bw;
    const int bnl = hi ? bn - 512 : bn;
    const float* be = hi ? bias2 : bias;
    float* Ce = hi ? C2 : C;
    const int ldce = hi ? ldc2 : ldc;

    float d[4][4][4];
    #pragma unroll
    for (int i = 0; i < 4; i++)
        #pragma unroll
        for (int j = 0; j < 4; j++)
            #pragma unroll
            for (int r = 0; r < 4; r++) d[i][j][r] = 0.f;

    const uint32_t sbase = (uint32_t)__cvta_generic_to_shared(smemu);

    // ---- staging mapping (identical addresses to R9): thread t -> row t>>1,
    // k-half t&1; two 16B quads per matrix per chunk via cp.async ----
    const int s_row = tid >> 1;
    const int s_kh  = tid & 1;
    const int s_sw  = (s_row >> 1) & 3;
    const float* aptr = A   + (size_t)(bm  + s_row) * lda + s_kh * 8;
    const float* bptr = Bwe + (size_t)(bnl + s_row) * ldb + s_kh * 8;
    const uint32_t aD0 = sbase + s_row * 64 + (((2 * s_kh)     ^ s_sw) << 4);
    const uint32_t aD1 = sbase + s_row * 64 + (((2 * s_kh + 1) ^ s_sw) << 4);

    auto issue = [&](int c, int s) {
        const uint32_t st = (uint32_t)(s * 8192);
        const float* ap = aptr + c * 16;
        const float* bp = bptr + c * 16;
        CPA16(aD0 + st, ap);
        CPA16(aD1 + st, ap + 4);
        CPA16(aD0 + 16384 + st, bp);
        CPA16(aD1 + 16384 + st, bp + 4);
    };

    // ---- ldmatrix per-lane address components (R9-verified mapping) ----
    const int rowAin = ((lane >> 3) & 1) * 8 + (lane & 7);
    const int qhA = lane >> 4;
    const int rowBin = (lane >> 4) * 8 + (lane & 7);
    const int qhB = (lane >> 3) & 1;
    const int swL = ((lane & 7) >> 1) & 3;
    const uint32_t aAddr0 = sbase + (wm * 64 + rowAin) * 64;
    const uint32_t bAddr0 = sbase + 16384 + (wn * 32 + rowBin) * 64;

    const int nc = K >> 4;
    issue(0, 0); CPCOMMIT();

    for (int c = 0; c < nc; c++) {
        CPWAIT0();
        __syncthreads();   // stage c&1 filled; all warps done reading (c+1)&1
        if (c + 1 < nc) { issue(c + 1, (c + 1) & 1); CPCOMMIT(); }

        const uint32_t st = (uint32_t)((c & 1) * 8192);
        #pragma unroll
        for (int ks = 0; ks < 2; ks++) {
            const uint32_t aOff = aAddr0 + st + (((2 * ks + qhA) ^ swL) << 4);
            const uint32_t bOff = bAddr0 + st + (((2 * ks + qhB) ^ swL) << 4);
            uint32_t a[4][4], b[2][4];
            #pragma unroll
            for (int mt = 0; mt < 4; mt++)
                LDSM4(a[mt][0], a[mt][1], a[mt][2], a[mt][3], aOff + mt * 1024);
            #pragma unroll
            for (int pr = 0; pr < 2; pr++)
                LDSM4(b[pr][0], b[pr][1], b[pr][2], b[pr][3], bOff + pr * 1024);
            #pragma unroll
            for (int mt = 0; mt < 4; mt++)
                #pragma unroll
                for (int j = 0; j < 4; j++)
                    a[mt][j] = cvt_u(a[mt][j]);
            // B pre-rounded tf32 in gmem: no cvt.
            #pragma unroll
            for (int mt = 0; mt < 4; mt++)
                #pragma unroll
                for (int nt = 0; nt < 4; nt++)
                    mma_tf32(d[mt][nt], a[mt], &b[nt >> 1][(nt & 1) * 2]);
        }
    }

    // epilogue
    const int mbase = wm * 64, nbase = wn * 32;
    #pragma unroll
    for (int mt = 0; mt < 4; mt++) {
        #pragma unroll
        for (int half = 0; half < 2; half++) {
            const int m = bm + mbase + mt * 16 + g + half * 8;
            float* crow = Ce + (size_t)m * ldce;
            const float* rrow = resid ? resid + (size_t)m * ldr : nullptr;
            #pragma unroll
            for (int nt = 0; nt < 4; nt++) {
                const int n = bnl + nbase + nt * 8 + t4 * 2;
                float vx = d[mt][nt][half * 2 + 0];
                float vy = d[mt][nt][half * 2 + 1];
                if (be)   { vx += be[n]; vy += be[n + 1]; }
                if (rrow) { vx += rrow[n]; vy += rrow[n + 1]; }
                if (relu) { vx = fmaxf(vx, 0.f); vy = fmaxf(vy, 0.f); }
                *(float2*)(crow + n) = make_float2(vx, vy);
            }
        }
    }
}

// --------------------- round weights to tf32 (once per launch) --------------
__global__ void round_tf32(const float* __restrict__ in, float* __restrict__ out, int n) {
    int i = blockIdx.x * 256 + threadIdx.x;
    if (i < n) out[i] = __uint_as_float(f2tf32(in[i]));
}

// ------------------------- transpose NCHW -> (B,N,C) ------------------------
__global__ void transpose_cn_to_nc(const float* __restrict__ in, float* __restrict__ out) {
    __shared__ float tile[32][33];
    int b = blockIdx.z;
    int n0 = blockIdx.x * 32, c0 = blockIdx.y * 32;
    const float* ip = in + (size_t)b * Cc * Nn;
    float* op = out + (size_t)b * Nn * Cc;
    int tx = threadIdx.x, ty = threadIdx.y;
    #pragma unroll
    for (int i = ty; i < 32; i += 8)
        tile[i][tx] = ip[(size_t)(c0 + i) * Nn + n0 + tx];
    __syncthreads();
    #pragma unroll
    for (int i = ty; i < 32; i += 8)
        op[(size_t)(n0 + i) * Cc + c0 + tx] = tile[tx][i];
}

// --------------------------- attention: kT v partials -----------------------
__global__ __launch_bounds__(256) void attn_ktv(const float* __restrict__ kv,
                                                float* __restrict__ part) {
    __shared__ float ks[32][68];
    __shared__ float vs[32][68];
    int bh = blockIdx.x;
    int b = bh >> 3, h = bh & 7;
    int s = blockIdx.y;
    const float* kp = kv + (size_t)b * Nn * 1024 + h * 64;
    const float* vp = kp + 512;
    int tid = threadIdx.x;
    int td = tid >> 4, te = tid & 15;
    float acc[4][4];
    #pragma unroll
    for (int i = 0; i < 4; i++)
        #pragma unroll
        for (int j = 0; j < 4; j++) acc[i][j] = 0.f;

    for (int n0 = s * 256; n0 < s * 256 + 256; n0 += 32) {
        #pragma unroll
        for (int hh = 0; hh < 2; hh++) {
            int flat = tid + 256 * hh;
            int row = flat >> 4;
            int cv = (flat & 15) << 2;
            *(float4*)&ks[row][cv] = *(const float4*)(kp + (size_t)(n0 + row) * 1024 + cv);
            *(float4*)&vs[row][cv] = *(const float4*)(vp + (size_t)(n0 + row) * 1024 + cv);
        }
        __syncthreads();
        #pragma unroll
        for (int nn = 0; nn < 32; nn++) {
            float av[4], bv[4];
            float4 a4 = *(float4*)&ks[nn][td * 4];
            av[0]=a4.x; av[1]=a4.y; av[2]=a4.z; av[3]=a4.w;
            float4 b4 = *(float4*)&vs[nn][te * 4];
            bv[0]=b4.x; bv[1]=b4.y; bv[2]=b4.z; bv[3]=b4.w;
            #pragma unroll
            for (int i = 0; i < 4; i++)
                #pragma unroll
                for (int j = 0; j < 4; j++)
                    acc[i][j] += av[i] * bv[j];
        }
        __syncthreads();
    }
    float* pp = part + ((size_t)bh * 16 + s) * 4096;
    #pragma unroll
    for (int i = 0; i < 4; i++)
        #pragma unroll
        for (int j = 0; j < 4; j++)
            pp[(td * 4 + i) * 64 + te * 4 + j] = acc[i][j];
}

__global__ void attn_reduce_softmax(const float* __restrict__ part,
                                    float* __restrict__ ctx) {
    int bh = blockIdx.x;
    int e = threadIdx.x;
    float m[64];
    #pragma unroll
    for (int d = 0; d < 64; d++) {
        float ssum = 0.f;
        #pragma unroll
        for (int p = 0; p < 16; p++)
            ssum += part[((size_t)bh * 16 + p) * 4096 + d * 64 + e];
        m[d] = ssum * 0.125f;
    }
    float mx = -1e30f;
    #pragma unroll
    for (int d = 0; d < 64; d++) mx = fmaxf(mx, m[d]);
    float sum = 0.f;
    #pragma unroll
    for (int d = 0; d < 64; d++) { m[d] = expf(m[d] - mx); sum += m[d]; }
    float inv = 1.f / sum;
    #pragma unroll
    for (int d = 0; d < 64; d++)
        ctx[(size_t)bh * 4096 + d * 64 + e] = m[d] * inv;
}

__global__ __launch_bounds__(256) void attn_qctx(const float* __restrict__ q,
                                                 const float* __restrict__ ctx,
                                                 float* __restrict__ outp) {
    __shared__ float cs[64][68];
    __shared__ float qs[64][68];
    int bh = blockIdx.y;
    int b = bh >> 3, h = bh & 7;
    const float* cp = ctx + (size_t)bh * 4096;
    int tid = threadIdx.x;
    for (int i = tid; i < 4096; i += 256)
        cs[i >> 6][i & 63] = cp[i];
    int n0 = blockIdx.x * 64;
    const float* qp = q + (size_t)b * Nn * Cc + h * 64;
    #pragma unroll
    for (int j = 0; j < 4; j++) {
        int flat = tid + 256 * j;
        int row = flat >> 4;
        int cv = (flat & 15) << 2;
        *(float4*)&qs[row][cv] = *(const float4*)(qp + (size_t)(n0 + row) * Cc + cv);
    }
    __syncthreads();
    int tn = tid >> 3;
    int te = tid & 7;
    float acc0[8], acc1[8];
    #pragma unroll
    for (int j = 0; j < 8; j++) { acc0[j] = 0.f; acc1[j] = 0.f; }
    #pragma unroll 4
    for (int d = 0; d < 64; d++) {
        float qa = qs[tn][d];
        float qb = qs[tn + 32][d];
        float4 c0 = *(float4*)&cs[d][te * 8];
        float4 c1 = *(float4*)&cs[d][te * 8 + 4];
        float cv[8];
        cv[0]=c0.x; cv[1]=c0.y; cv[2]=c0.z; cv[3]=c0.w;
        cv[4]=c1.x; cv[5]=c1.y; cv[6]=c1.z; cv[7]=c1.w;
        #pragma unroll
        for (int j = 0; j < 8; j++) {
            acc0[j] += qa * cv[j];
            acc1[j] += qb * cv[j];
        }
    }
    float* o0 = outp + ((size_t)b * Nn + n0 + tn) * 1024 + h * 64 + te * 8;
    float* o1 = outp + ((size_t)b * Nn + n0 + tn + 32) * 1024 + h * 64 + te * 8;
    #pragma unroll
    for (int j = 0; j < 8; j++) { o0[j] = acc0[j]; o1[j] = acc1[j]; }
}

// ------------------------------ layernorm rows ------------------------------
__global__ __launch_bounds__(128) void layernorm_rows(float* __restrict__ base, int ld,
                                                      const float* __restrict__ gg,
                                                      const float* __restrict__ bb) {
    int row = blockIdx.x;
    float* p = base + (size_t)row * ld;
    int t = threadIdx.x;
    float v[4];
    float s = 0.f;
    #pragma unroll
    for (int i = 0; i < 4; i++) { v[i] = p[t + i * 128]; s += v[i]; }
    __shared__ float red[4];
    #pragma unroll
    for (int o = 16; o > 0; o >>= 1) s += __shfl_xor_sync(0xffffffffu, s, o);
    if ((t & 31) == 0) red[t >> 5] = s;
    __syncthreads();
    float mu = (red[0] + red[1] + red[2] + red[3]) * (1.f / 512.f);
    float q = 0.f;
    #pragma unroll
    for (int i = 0; i < 4; i++) { float d = v[i] - mu; q += d * d; }
    #pragma unroll
    for (int o = 16; o > 0; o >>= 1) q += __shfl_xor_sync(0xffffffffu, q, o);
    __syncthreads();
    if ((t & 31) == 0) red[t >> 5] = q;
    __syncthreads();
    float rs = rsqrtf((red[0] + red[1] + red[2] + red[3]) * (1.f / 512.f) + 1e-5f);
    #pragma unroll
    for (int i = 0; i < 4; i++) {
        int c = t + i * 128;
        p[c] = (v[i] - mu) * rs * gg[c] + bb[c];
    }
}

// --------------------------- depthwise 3x3 + relu ---------------------------
__global__ void dwconv3x3(const float* __restrict__ in, const float* __restrict__ w,
                          const float* __restrict__ bias, float* __restrict__ out) {
    int idx = blockIdx.x * 256 + threadIdx.x;
    int c = idx & 511;
    int n = (idx >> 9) & 4095;
    int b = idx >> 21;
    int h = n >> 6, ww = n & 63;
    float acc = bias[c];
    #pragma unroll
    for (int kh = 0; kh < 3; kh++) {
        int hh = h + kh - 1;
        if ((unsigned)hh >= 64u) continue;
        #pragma unroll
        for (int kw = 0; kw < 3; kw++) {
            int wc = ww + kw - 1;
            if ((unsigned)wc >= 64u) continue;
            acc += in[((size_t)b * Nn + hh * 64 + wc) * Cc + c] * w[c * 9 + kh * 3 + kw];
        }
    }
    out[idx] = fmaxf(acc, 0.f);
}

// ------------------------------- batchnorm ----------------------------------
__global__ __launch_bounds__(256) void bn_stats_partial(const float* __restrict__ X,
                                                        float* __restrict__ part) {
    int blk = blockIdx.x;
    const float* p = X + (size_t)blk * 128 * Cc;
    int c0 = threadIdx.x, c1 = threadIdx.x + 256;
    float s0 = 0.f, q0 = 0.f, s1 = 0.f, q1 = 0.f;
    for (int r = 0; r < 128; r++) {
        float a = p[(size_t)r * Cc + c0];
        s0 += a; q0 += a * a;
        float bv = p[(size_t)r * Cc + c1];
        s1 += bv; q1 += bv * bv;
    }
    part[(size_t)blk * Cc + c0] = s0;
    part[(size_t)blk * Cc + c1] = s1;
    part[(size_t)256 * Cc + blk * Cc + c0] = q0;
    part[(size_t)256 * Cc + blk * Cc + c1] = q1;
}

__global__ void bn_stats_final(const float* __restrict__ part,
                               float* __restrict__ mu, float* __restrict__ rs) {
    int c = threadIdx.x;
    float s = 0.f, q = 0.f;
    for (int p = 0; p < 256; p++) {
        s += part[(size_t)p * Cc + c];
        q += part[(size_t)256 * Cc + p * Cc + c];
    }
    float m = s * (1.f / 32768.f);
    float v = q * (1.f / 32768.f) - m * m;
    mu[c] = m;
    rs[c] = rsqrtf(v + 1e-5f);
}

// s = resid + bn1(t3), and per-block partial sums/sumsq of s (for bn2)
__global__ __launch_bounds__(256) void bn_apply_add_stats(
    const float* __restrict__ t3, const float* __restrict__ res,
    const float* __restrict__ mu, const float* __restrict__ rs,
    const float* __restrict__ gg, const float* __restrict__ bb,
    float* __restrict__ s, float* __restrict__ part) {
    int blk = blockIdx.x;
    const size_t base = (size_t)blk * 128 * Cc;
    int c0 = threadIdx.x, c1 = threadIdx.x + 256;
    float m0 = mu[c0], r0 = rs[c0], g0 = gg[c0], e0 = bb[c0];
    float m1 = mu[c1], r1 = rs[c1], g1 = gg[c1], e1 = bb[c1];
    float s0 = 0.f, q0 = 0.f, s1 = 0.f, q1 = 0.f;
    for (int r = 0; r < 128; r++) {
        size_t i0 = base + (size_t)r * Cc + c0;
        float v0 = res[i0] + (t3[i0] - m0) * r0 * g0 + e0;
        s[i0] = v0; s0 += v0; q0 += v0 * v0;
        size_t i1 = base + (size_t)r * Cc + c1;
        float v1 = res[i1] + (t3[i1] - m1) * r1 * g1 + e1;
        s[i1] = v1; s1 += v1; q1 += v1 * v1;
    }
    part[(size_t)blk * Cc + c0] = s0;
    part[(size_t)blk * Cc + c1] = s1;
    part[(size_t)256 * Cc + blk * Cc + c0] = q0;
    part[(size_t)256 * Cc + blk * Cc + c1] = q1;
}

__global__ void bn_apply_transpose(const float* __restrict__ s,
                                   const float* __restrict__ mu, const float* __restrict__ rs,
                                   const float* __restrict__ gg, const float* __restrict__ bb,
                                   float* __restrict__ out) {
    __shared__ float tile[32][33];
    int b = blockIdx.z;
    int n0 = blockIdx.x * 32, c0 = blockIdx.y * 32;
    const float* ps = s + (size_t)b * Nn * Cc;
    float* po = out + (size_t)b * Cc * Nn;
    int tx = threadIdx.x, ty = threadIdx.y;
    #pragma unroll
    for (int i = ty; i < 32; i += 8) {
        int c = c0 + tx;
        float v = ps[(size_t)(n0 + i) * Cc + c];
        tile[i][tx] = (v - mu[c]) * rs[c] * gg[c] + bb[c];
    }
    __syncthreads();
    #pragma unroll
    for (int i = ty; i < 32; i += 8)
        po[(size_t)(c0 + i) * Nn + n0 + tx] = tile[tx][i];
}

// --------------------------------- launch -----------------------------------
static void tc_go(const float* A, int lda,
                  const float* Bw, const float* Bw2, int ldb,
                  const float* bias, const float* bias2,
                  const float* resid, int ldr,
                  float* C, int ldc, float* C2, int ldc2,
                  int M, int Ngemm, int K, int relu) {
    tc_gemm<<<dim3(Ngemm / 128, M / 128), 256>>>(
        A, lda, Bw, Bw2, ldb, bias, bias2, resid, ldr, C, ldc, C2, ldc2, K, relu);
}

extern "C" void kernel_launch(void* const* d_in, const int* in_sizes, int n_in,
                              void* d_out, int out_size) {
    (void)in_sizes; (void)n_in; (void)out_size;
    const float* rgb        = (const float*)d_in[0];
    const float* x          = (const float*)d_in[1];
    const float* W_rgb_proj = (const float*)d_in[2];
    const float* b_rgb_proj = (const float*)d_in[3];
    const float* W_x_proj   = (const float*)d_in[4];
    const float* b_x_proj   = (const float*)d_in[5];
    const float* W_kv_rgb   = (const float*)d_in[6];
    const float* W_kv_x     = (const float*)d_in[7];
    const float* W_out_rgb  = (const float*)d_in[8];
    const float* b_out_rgb  = (const float*)d_in[9];
    const float* W_out_x    = (const float*)d_in[10];
    const float* b_out_x    = (const float*)d_in[11];
    const float* ln_rgb_g   = (const float*)d_in[12];
    const float* ln_rgb_b   = (const float*)d_in[13];
    const float* ln_x_g     = (const float*)d_in[14];
    const float* ln_x_b     = (const float*)d_in[15];
    const float* W_res      = (const float*)d_in[16];
    const float* W_ce1      = (const float*)d_in[17];
    const float* b_ce1      = (const float*)d_in[18];
    const float* W_dw       = (const float*)d_in[19];
    const float* b_dw       = (const float*)d_in[20];
    const float* W_ce2      = (const float*)d_in[21];
    const float* b_ce2      = (const float*)d_in[22];
    const float* bn1_g      = (const float*)d_in[23];
    const float* bn1_b      = (const float*)d_in[24];
    const float* bn2_g      = (const float*)d_in[25];
    const float* bn2_b      = (const float*)d_in[26];
    float* out = (float*)d_out;

    float *p_r, *p_x, *p_yr, *p_yx, *p_ur, *p_ux, *p_kvr, *p_kvx;
    float *p_ctx, *p_attp, *p_fuse, *p_res, *p_t1, *p_t2, *p_bnp, *p_mu, *p_rs, *p_w;
    cudaGetSymbolAddress((void**)&p_r,    g_r);
    cudaGetSymbolAddress((void**)&p_x,    g_x);
    cudaGetSymbolAddress((void**)&p_yr,   g_yr);
    cudaGetSymbolAddress((void**)&p_yx,   g_yx);
    cudaGetSymbolAddress((void**)&p_ur,   g_ur);
    cudaGetSymbolAddress((void**)&p_ux,   g_ux);
    cudaGetSymbolAddress((void**)&p_kvr,  g_kvr);
    cudaGetSymbolAddress((void**)&p_kvx,  g_kvx);
    cudaGetSymbolAddress((void**)&p_ctx,  g_ctx);
    cudaGetSymbolAddress((void**)&p_attp, g_attp);
    cudaGetSymbolAddress((void**)&p_fuse, g_fuse);
    cudaGetSymbolAddress((void**)&p_res,  g_res);
    cudaGetSymbolAddress((void**)&p_t1,   g_t1);
    cudaGetSymbolAddress((void**)&p_t2,   g_t2);
    cudaGetSymbolAddress((void**)&p_bnp,  g_bnp);
    cudaGetSymbolAddress((void**)&p_mu,   g_mu);
    cudaGetSymbolAddress((void**)&p_rs,   g_rs);
    cudaGetSymbolAddress((void**)&p_w,    g_w);

    // rounded weight copies
    float* w_rgb  = p_w;
    float* w_x    = p_w + 524288;
    float* w_kvr  = p_w + 1048576;
    float* w_kvx  = p_w + 1572864;
    float* w_outr = p_w + 2097152;
    float* w_outx = p_w + 2621440;
    float* w_res  = p_w + 3145728;
    float* w_ce1  = p_w + 3670016;
    float* w_ce2  = p_w + 4194304;
    round_tf32<<<2048, 256>>>(W_rgb_proj, w_rgb,  524288);
    round_tf32<<<2048, 256>>>(W_x_proj,   w_x,    524288);
    round_tf32<<<2048, 256>>>(W_kv_rgb,   w_kvr,  524288);
    round_tf32<<<2048, 256>>>(W_kv_x,     w_kvx,  524288);
    round_tf32<<<2048, 256>>>(W_out_rgb,  w_outr, 524288);
    round_tf32<<<2048, 256>>>(W_out_x,    w_outx, 524288);
    round_tf32<<<2048, 256>>>(W_res,      w_res,  524288);
    round_tf32<<<2048, 256>>>(W_ce1,      w_ce1,  524288);
    round_tf32<<<1024, 256>>>(W_ce2,      w_ce2,  262144);

    dim3 tp_grid(128, 16, 8), tp_blk(32, 8);

    // 1. transposes
    transpose_cn_to_nc<<<tp_grid, tp_blk>>>(rgb, p_r);
    transpose_cn_to_nc<<<tp_grid, tp_blk>>>(x,   p_x);

    // 2. fused projections: cols 0..511 -> y (ld 1024), 512..1023 -> u (ld 512)
    tc_go(p_r, 512, w_rgb, w_rgb + 262144, 512,
          b_rgb_proj, b_rgb_proj + 512, nullptr, 0,
          p_yr, 1024, p_ur, 512, 32768, 1024, 512, 1);
    tc_go(p_x, 512, w_x, w_x + 262144, 512,
          b_x_proj, b_x_proj + 512, nullptr, 0,
          p_yx, 1024, p_ux, 512, 32768, 1024, 512, 1);

    // 3. kv projections
    tc_go(p_ur, 512, w_kvr, nullptr, 512, nullptr, nullptr, nullptr, 0,
          p_kvr, 1024, nullptr, 0, 32768, 1024, 512, 0);
    tc_go(p_ux, 512, w_kvx, nullptr, 512, nullptr, nullptr, nullptr, 0,
          p_kvx, 1024, nullptr, 0, 32768, 1024, 512, 0);

    // 4. attention (exact fp32)
    attn_ktv<<<dim3(64, 16), 256>>>(p_kvr, p_attp);
    attn_ktv<<<dim3(64, 16), 256>>>(p_kvx, p_attp + (size_t)64 * 16 * 4096);
    attn_reduce_softmax<<<64, 64>>>(p_attp,                          p_ctx);
    attn_reduce_softmax<<<64, 64>>>(p_attp + (size_t)64 * 16 * 4096, p_ctx + 64 * 4096);
    attn_qctx<<<dim3(64, 64), 256>>>(p_ur, p_ctx + 64 * 4096, p_yr + 512);  // o_rgb
    attn_qctx<<<dim3(64, 64), 256>>>(p_ux, p_ctx,             p_yx + 512);  // o_x

    // 5. out projections + residual, then LN
    tc_go(p_yr, 1024, w_outr, nullptr, 1024, b_out_rgb, nullptr, p_r, 512,
          p_fuse, 1024, nullptr, 0, 32768, 512, 1024, 0);
    tc_go(p_yx, 1024, w_outx, nullptr, 1024, b_out_x, nullptr, p_x, 512,
          p_fuse + 512, 1024, nullptr, 0, 32768, 512, 1024, 0);
    layernorm_rows<<<32768, 128>>>(p_fuse,       1024, ln_rgb_g, ln_rgb_b);
    layernorm_rows<<<32768, 128>>>(p_fuse + 512, 1024, ln_x_g,   ln_x_b);

    // 6. fused residual + ce1 (split weights), then CE block
    tc_go(p_fuse, 1024, w_res, w_ce1, 1024, nullptr, b_ce1, nullptr, 0,
          p_res, 512, p_t1, 512, 32768, 1024, 1024, 0);
    dwconv3x3<<<65536, 256>>>(p_t1, W_dw, b_dw, p_t2);
    tc_go(p_t2, 512, w_ce2, nullptr, 512, b_ce2, nullptr, nullptr, 0,
          p_t1, 512, nullptr, 0, 32768, 512, 512, 0);

    // 7. bn1 stats, fused apply+residual+bn2-stats, bn2 apply + transpose
    bn_stats_partial<<<256, 256>>>(p_t1, p_bnp);
    bn_stats_final<<<1, 512>>>(p_bnp, p_mu, p_rs);
    bn_apply_add_stats<<<256, 256>>>(p_t1, p_res, p_mu, p_rs, bn1_g, bn1_b, p_t2, p_bnp);
    bn_stats_final<<<1, 512>>>(p_bnp, p_mu, p_rs);
    bn_apply_transpose<<<tp_grid, tp_blk>>>(p_t2, p_mu, p_rs, bn2_g, bn2_b, out);
}